// round 1
// baseline (speedup 1.0000x reference)
#include <cuda_runtime.h>
#include <math.h>

// Problem constants
#define BB   2
#define SS   2048
#define DM   1024
#define NH   16
#define HDIM 64

// Scratch for projected Q, K, V (device globals: allocation-free)
__device__ float g_q[BB * SS * DM];
__device__ float g_k[BB * SS * DM];
__device__ float g_v[BB * SS * DM];

// ---------------------------------------------------------------------------
// GEMM NT with bias: Y[M,N] = X[M,K] @ W[N,K]^T + bias[N]
// 128x128 tile, BK=16, 256 threads, 8x8 per-thread register tile.
// ---------------------------------------------------------------------------
#define GBM 128
#define GBN 128
#define GBK 16

__global__ __launch_bounds__(256) void gemm_nt_bias(
    const float* __restrict__ X, const float* __restrict__ W,
    const float* __restrict__ bias, float* __restrict__ Y,
    int M, int N, int K)
{
    __shared__ float As[GBK][GBM];
    __shared__ float Bs[GBK][GBN];

    const int tid = threadIdx.x;
    const int tx = tid & 15;          // 0..15  -> N direction
    const int ty = tid >> 4;          // 0..15  -> M direction
    const int m0 = blockIdx.y * GBM;
    const int n0 = blockIdx.x * GBN;

    float acc[8][8];
#pragma unroll
    for (int i = 0; i < 8; i++)
#pragma unroll
        for (int j = 0; j < 8; j++) acc[i][j] = 0.0f;

    for (int k0 = 0; k0 < K; k0 += GBK) {
        // Load tiles: 128 rows x 16 k each; 512 float4 per tile; 2 per thread.
#pragma unroll
        for (int i = 0; i < 2; i++) {
            int f   = tid * 2 + i;     // 0..511
            int row = f >> 2;          // 0..127
            int kq  = (f & 3) * 4;     // 0,4,8,12
            float4 va = *(const float4*)&X[(size_t)(m0 + row) * K + k0 + kq];
            As[kq + 0][row] = va.x;
            As[kq + 1][row] = va.y;
            As[kq + 2][row] = va.z;
            As[kq + 3][row] = va.w;
            float4 vb = *(const float4*)&W[(size_t)(n0 + row) * K + k0 + kq];
            Bs[kq + 0][row] = vb.x;
            Bs[kq + 1][row] = vb.y;
            Bs[kq + 2][row] = vb.z;
            Bs[kq + 3][row] = vb.w;
        }
        __syncthreads();

#pragma unroll
        for (int k = 0; k < GBK; k++) {
            float a[8], b[8];
            *(float4*)&a[0] = *(float4*)&As[k][ty * 8];
            *(float4*)&a[4] = *(float4*)&As[k][ty * 8 + 4];
            *(float4*)&b[0] = *(float4*)&Bs[k][tx * 8];
            *(float4*)&b[4] = *(float4*)&Bs[k][tx * 8 + 4];
#pragma unroll
            for (int i = 0; i < 8; i++)
#pragma unroll
                for (int j = 0; j < 8; j++)
                    acc[i][j] = fmaf(a[i], b[j], acc[i][j]);
        }
        __syncthreads();
    }

#pragma unroll
    for (int i = 0; i < 8; i++) {
        int m = m0 + ty * 8 + i;
#pragma unroll
        for (int j = 0; j < 8; j++) {
            int n = n0 + tx * 8 + j;
            Y[(size_t)m * N + n] = acc[i][j] + bias[n];
        }
    }
}

// ---------------------------------------------------------------------------
// Flash attention, fp32, causal. One CTA per (b, h, 64-row q tile).
// 256 threads = 16x16; each thread owns a 4x4 tile of the 64x64 score block
// and a 4x4 tile of the 64x64 (rows x headdim) output block.
// smem: qT [d][r], kT/p shared buffer, v [c][d]; stride 68 for bank spread.
// ---------------------------------------------------------------------------
#define AT   64
#define APAD 68
#define ATT_SMEM (3 * AT * APAD * (int)sizeof(float))

__global__ __launch_bounds__(256) void flash_attn_kernel(
    const float* __restrict__ Q, const float* __restrict__ K,
    const float* __restrict__ V, float* __restrict__ O)
{
    extern __shared__ float sm[];
    float* qst = sm;                 // [AT][APAD]: qst[d*APAD + r]
    float* kps = sm + AT * APAD;     // kT[d*APAD + c]  then reused as p[r*APAD + c]
    float* vs  = sm + 2 * AT * APAD; // v [c*APAD + d]

    const int tid = threadIdx.x;
    const int tx = tid & 15;
    const int ty = tid >> 4;
    const int qt = (int)gridDim.x - 1 - (int)blockIdx.x;  // heavy tiles first
    const int h  = blockIdx.y;
    const int b  = blockIdx.z;

    const float scale = 0.03125f;            // 1/sqrt(1024)
    const float NEG   = -3.0e38f;

    const float* Qb = Q + ((size_t)(b * SS) + qt * AT) * DM + h * HDIM;

    float o[4][4];
    float mrow[4], lrow[4];
#pragma unroll
    for (int i = 0; i < 4; i++) {
        mrow[i] = NEG;
        lrow[i] = 0.0f;
#pragma unroll
        for (int j = 0; j < 4; j++) o[i][j] = 0.0f;
    }

    // Load Q tile transposed: qst[d][r]
    {
        int d4 = (tid & 15) * 4;
        int r0 = tid >> 4;
#pragma unroll
        for (int rr = 0; rr < 4; rr++) {
            int r = r0 + rr * 16;
            float4 v = *(const float4*)&Qb[(size_t)r * DM + d4];
            qst[(d4 + 0) * APAD + r] = v.x;
            qst[(d4 + 1) * APAD + r] = v.y;
            qst[(d4 + 2) * APAD + r] = v.z;
            qst[(d4 + 3) * APAD + r] = v.w;
        }
    }

    for (int kt = 0; kt <= qt; kt++) {
        __syncthreads();   // protect kps/vs reuse from previous iteration
        const float* Kb = K + ((size_t)(b * SS) + kt * AT) * DM + h * HDIM;
        const float* Vb = V + ((size_t)(b * SS) + kt * AT) * DM + h * HDIM;
        {
            int d4 = (tid & 15) * 4;
            int r0 = tid >> 4;
#pragma unroll
            for (int rr = 0; rr < 4; rr++) {
                int r = r0 + rr * 16;
                float4 kv = *(const float4*)&Kb[(size_t)r * DM + d4];
                kps[(d4 + 0) * APAD + r] = kv.x;
                kps[(d4 + 1) * APAD + r] = kv.y;
                kps[(d4 + 2) * APAD + r] = kv.z;
                kps[(d4 + 3) * APAD + r] = kv.w;
                float4 vv = *(const float4*)&Vb[(size_t)r * DM + d4];
                *(float4*)&vs[r * APAD + d4] = vv;
            }
        }
        __syncthreads();

        // Scores: s[i][j] = sum_d qT[d][4ty+i] * kT[d][4tx+j]
        float s[4][4];
#pragma unroll
        for (int i = 0; i < 4; i++)
#pragma unroll
            for (int j = 0; j < 4; j++) s[i][j] = 0.0f;

#pragma unroll 8
        for (int d = 0; d < AT; d++) {
            float4 a  = *(float4*)&qst[d * APAD + ty * 4];
            float4 bb = *(float4*)&kps[d * APAD + tx * 4];
            float av[4] = {a.x, a.y, a.z, a.w};
            float bv[4] = {bb.x, bb.y, bb.z, bb.w};
#pragma unroll
            for (int i = 0; i < 4; i++)
#pragma unroll
                for (int j = 0; j < 4; j++)
                    s[i][j] = fmaf(av[i], bv[j], s[i][j]);
        }
        __syncthreads();   // everyone done reading kps; it becomes p-buffer

        const bool diag = (kt == qt);
#pragma unroll
        for (int i = 0; i < 4; i++) {
#pragma unroll
            for (int j = 0; j < 4; j++) {
                float sv = s[i][j] * scale;
                if (diag && (tx * 4 + j) > (ty * 4 + i)) sv = NEG;
                s[i][j] = sv;
            }
        }

        // Online softmax per row (reduce across the 16 tx lanes)
#pragma unroll
        for (int i = 0; i < 4; i++) {
            float rmax = fmaxf(fmaxf(s[i][0], s[i][1]), fmaxf(s[i][2], s[i][3]));
#pragma unroll
            for (int msk = 1; msk < 16; msk <<= 1)
                rmax = fmaxf(rmax, __shfl_xor_sync(0xffffffffu, rmax, msk));
            float mn   = fmaxf(mrow[i], rmax);
            float corr = __expf(mrow[i] - mn);
            float rsum = 0.0f;
#pragma unroll
            for (int j = 0; j < 4; j++) {
                s[i][j] = __expf(s[i][j] - mn);
                rsum += s[i][j];
            }
#pragma unroll
            for (int msk = 1; msk < 16; msk <<= 1)
                rsum += __shfl_xor_sync(0xffffffffu, rsum, msk);
            lrow[i] = lrow[i] * corr + rsum;
            mrow[i] = mn;
#pragma unroll
            for (int j = 0; j < 4; j++) o[i][j] *= corr;
            // store p row-major: p[r][c]
            *(float4*)&kps[(ty * 4 + i) * APAD + tx * 4] =
                make_float4(s[i][0], s[i][1], s[i][2], s[i][3]);
        }
        __syncthreads();

        // o[i][j] += sum_c p[4ty+i][c] * v[c][4tx+j]
#pragma unroll 8
        for (int c = 0; c < AT; c++) {
            float4 bv = *(float4*)&vs[c * APAD + tx * 4];
            float bvv[4] = {bv.x, bv.y, bv.z, bv.w};
#pragma unroll
            for (int i = 0; i < 4; i++) {
                float av = kps[(ty * 4 + i) * APAD + c];
#pragma unroll
                for (int j = 0; j < 4; j++)
                    o[i][j] = fmaf(av, bvv[j], o[i][j]);
            }
        }
    }

    // Epilogue: divide by l, write [B,S,D] with head-major packing
    float* Ob = O + ((size_t)(b * SS) + qt * AT) * DM + h * HDIM;
#pragma unroll
    for (int i = 0; i < 4; i++) {
        float inv = 1.0f / lrow[i];
#pragma unroll
        for (int j = 0; j < 4; j++)
            Ob[(size_t)(ty * 4 + i) * DM + tx * 4 + j] = o[i][j] * inv;
    }
}

// ---------------------------------------------------------------------------
// kernel_launch
// inputs: 0 qx, 1 kx, 2 vx, 3 mask(int32, ignored: causal known),
//         4 Wq, 5 bq, 6 Wk, 7 bk, 8 Wv, 9 bv
// ---------------------------------------------------------------------------
extern "C" void kernel_launch(void* const* d_in, const int* in_sizes, int n_in,
                              void* d_out, int out_size)
{
    const float* qx = (const float*)d_in[0];
    const float* kx = (const float*)d_in[1];
    const float* vx = (const float*)d_in[2];
    const float* Wq = (const float*)d_in[4];
    const float* bq = (const float*)d_in[5];
    const float* Wk = (const float*)d_in[6];
    const float* bk = (const float*)d_in[7];
    const float* Wv = (const float*)d_in[8];
    const float* bv = (const float*)d_in[9];
    float* out = (float*)d_out;

    float *gq, *gk, *gv;
    cudaGetSymbolAddress((void**)&gq, g_q);
    cudaGetSymbolAddress((void**)&gk, g_k);
    cudaGetSymbolAddress((void**)&gv, g_v);

    const int M = BB * SS;   // 4096
    const int N = DM;        // 1024
    const int K = DM;        // 1024

    dim3 ggrid(N / GBN, M / GBM);   // (8, 32)
    gemm_nt_bias<<<ggrid, 256>>>(qx, Wq, bq, gq, M, N, K);
    gemm_nt_bias<<<ggrid, 256>>>(kx, Wk, bk, gk, M, N, K);
    gemm_nt_bias<<<ggrid, 256>>>(vx, Wv, bv, gv, M, N, K);

    cudaFuncSetAttribute(flash_attn_kernel,
                         cudaFuncAttributeMaxDynamicSharedMemorySize, ATT_SMEM);
    dim3 agrid(SS / AT, NH, BB);    // (32, 16, 2)
    flash_attn_kernel<<<agrid, 256, ATT_SMEM>>>(gq, gk, gv, out);
}

// round 3
// speedup vs baseline: 1.1319x; 1.1319x over previous
#include <cuda_runtime.h>
#include <math.h>
#include <stdint.h>

// Problem constants
#define BB   2
#define SS   2048
#define DM   1024
#define NH   16
#define HDIM 64

// Scratch for projected Q, K, V (device globals: allocation-free)
__device__ float g_q[BB * SS * DM];
__device__ float g_k[BB * SS * DM];
__device__ float g_v[BB * SS * DM];

// ---------------------------------------------------------------------------
// TF32 tensor-core GEMM NT with bias and 3-pass precision compensation:
//   Y[M,N] = X[M,K] @ W[N,K]^T + bias[N]
// CTA tile 128x64, BK=16, 256 threads (8 warps, 4x2 warp grid, 32x32/warp).
// Each warp: 2 m-tiles (m16) x 4 n-tiles (n8), k8 steps.
// Split x = hi + lo (13-bit split); D = Ahi*Bhi + Ahi*Blo + Alo*Bhi.
// ---------------------------------------------------------------------------
#define BM 128
#define BN 64
#define BK 16
#define KPAD 4   // smem row stride 20 words -> conflict-free fragment loads

__device__ __forceinline__ void tf32_split(float x, uint32_t& hi, uint32_t& lo) {
    uint32_t xh = __float_as_uint(x) & 0xFFFFE000u;
    hi = xh;
    lo = __float_as_uint(x - __uint_as_float(xh));
}

__device__ __forceinline__ void mma_tf32(float* c,
                                         uint32_t a0, uint32_t a1, uint32_t a2, uint32_t a3,
                                         uint32_t b0, uint32_t b1) {
    asm volatile(
        "mma.sync.aligned.m16n8k8.row.col.f32.tf32.tf32.f32 "
        "{%0,%1,%2,%3}, {%4,%5,%6,%7}, {%8,%9}, {%0,%1,%2,%3};\n"
        : "+f"(c[0]), "+f"(c[1]), "+f"(c[2]), "+f"(c[3])
        : "r"(a0), "r"(a1), "r"(a2), "r"(a3), "r"(b0), "r"(b1));
}

__global__ __launch_bounds__(256) void gemm_tf32_nt_bias(
    const float* __restrict__ X, const float* __restrict__ W,
    const float* __restrict__ bias, float* __restrict__ Y,
    int M, int N, int K)
{
    __shared__ __align__(16) float As[BM][BK + KPAD];
    __shared__ __align__(16) float Bs[BN][BK + KPAD];

    const int tid  = threadIdx.x;
    const int warp = tid >> 5;
    const int lane = tid & 31;
    const int wm = (warp >> 1) * 32;   // 0,32,64,96
    const int wn = (warp & 1) * 32;    // 0,32
    const int g  = lane >> 2;          // groupID 0..7
    const int tg = lane & 3;           // thread-in-group 0..3

    const int m0 = blockIdx.y * BM;
    const int n0 = blockIdx.x * BN;

    float c[2][4][4];
#pragma unroll
    for (int mt = 0; mt < 2; mt++)
#pragma unroll
        for (int nt = 0; nt < 4; nt++)
#pragma unroll
            for (int r = 0; r < 4; r++) c[mt][nt][r] = 0.0f;

    for (int k0 = 0; k0 < K; k0 += BK) {
        // Load A tile: 128 rows x 16 k = 512 float4; 2 per thread.
#pragma unroll
        for (int i = 0; i < 2; i++) {
            int f   = tid + i * 256;
            int row = f >> 2;
            int kq  = (f & 3) * 4;
            float4 v = *(const float4*)&X[(size_t)(m0 + row) * K + k0 + kq];
            *(float4*)&As[row][kq] = v;
        }
        // Load B tile: 64 rows x 16 k = 256 float4; 1 per thread.
        {
            int row = tid >> 2;
            int kq  = (tid & 3) * 4;
            float4 v = *(const float4*)&W[(size_t)(n0 + row) * K + k0 + kq];
            *(float4*)&Bs[row][kq] = v;
        }
        __syncthreads();

#pragma unroll
        for (int ks = 0; ks < 2; ks++) {
            const int kb = ks * 8;

            uint32_t ahi[2][4], alo[2][4];
#pragma unroll
            for (int mt = 0; mt < 2; mt++) {
                int r0 = wm + mt * 16;
                float x0 = As[r0 + g    ][kb + tg    ];
                float x1 = As[r0 + g + 8][kb + tg    ];
                float x2 = As[r0 + g    ][kb + tg + 4];
                float x3 = As[r0 + g + 8][kb + tg + 4];
                tf32_split(x0, ahi[mt][0], alo[mt][0]);
                tf32_split(x1, ahi[mt][1], alo[mt][1]);
                tf32_split(x2, ahi[mt][2], alo[mt][2]);
                tf32_split(x3, ahi[mt][3], alo[mt][3]);
            }

            uint32_t bhi[4][2], blo[4][2];
#pragma unroll
            for (int nt = 0; nt < 4; nt++) {
                int nr = wn + nt * 8 + g;
                float y0 = Bs[nr][kb + tg    ];
                float y1 = Bs[nr][kb + tg + 4];
                tf32_split(y0, bhi[nt][0], blo[nt][0]);
                tf32_split(y1, bhi[nt][1], blo[nt][1]);
            }

#pragma unroll
            for (int mt = 0; mt < 2; mt++)
#pragma unroll
                for (int nt = 0; nt < 4; nt++) {
                    mma_tf32(c[mt][nt], ahi[mt][0], ahi[mt][1], ahi[mt][2], ahi[mt][3],
                             bhi[nt][0], bhi[nt][1]);
                    mma_tf32(c[mt][nt], ahi[mt][0], ahi[mt][1], ahi[mt][2], ahi[mt][3],
                             blo[nt][0], blo[nt][1]);
                    mma_tf32(c[mt][nt], alo[mt][0], alo[mt][1], alo[mt][2], alo[mt][3],
                             bhi[nt][0], bhi[nt][1]);
                }
        }
        __syncthreads();
    }

    // Epilogue: c layout: c0=(g, tg*2), c1=(g, tg*2+1), c2=(g+8, ..), c3=(g+8, ..)
#pragma unroll
    for (int mt = 0; mt < 2; mt++) {
#pragma unroll
        for (int nt = 0; nt < 4; nt++) {
            int m = m0 + wm + mt * 16 + g;
            int n = n0 + wn + nt * 8 + tg * 2;
            float b0 = bias[n];
            float b1 = bias[n + 1];
            *(float2*)&Y[(size_t)m * N + n] =
                make_float2(c[mt][nt][0] + b0, c[mt][nt][1] + b1);
            *(float2*)&Y[(size_t)(m + 8) * N + n] =
                make_float2(c[mt][nt][2] + b0, c[mt][nt][3] + b1);
        }
    }
}

// ---------------------------------------------------------------------------
// Flash attention, fp32, causal. One CTA per (b, h, 64-row q tile).
// (unchanged from R1)
// ---------------------------------------------------------------------------
#define AT   64
#define APAD 68
#define ATT_SMEM (3 * AT * APAD * (int)sizeof(float))

__global__ __launch_bounds__(256) void flash_attn_kernel(
    const float* __restrict__ Q, const float* __restrict__ K,
    const float* __restrict__ V, float* __restrict__ O)
{
    extern __shared__ float sm[];
    float* qst = sm;                 // [AT][APAD]: qst[d*APAD + r]
    float* kps = sm + AT * APAD;     // kT[d*APAD + c]  then reused as p[r*APAD + c]
    float* vs  = sm + 2 * AT * APAD; // v [c*APAD + d]

    const int tid = threadIdx.x;
    const int tx = tid & 15;
    const int ty = tid >> 4;
    const int qt = (int)gridDim.x - 1 - (int)blockIdx.x;  // heavy tiles first
    const int h  = blockIdx.y;
    const int b  = blockIdx.z;

    const float scale = 0.03125f;            // 1/sqrt(1024)
    const float NEG   = -3.0e38f;

    const float* Qb = Q + ((size_t)(b * SS) + qt * AT) * DM + h * HDIM;

    float o[4][4];
    float mrow[4], lrow[4];
#pragma unroll
    for (int i = 0; i < 4; i++) {
        mrow[i] = NEG;
        lrow[i] = 0.0f;
#pragma unroll
        for (int j = 0; j < 4; j++) o[i][j] = 0.0f;
    }

    // Load Q tile transposed: qst[d][r]
    {
        int d4 = (tid & 15) * 4;
        int r0 = tid >> 4;
#pragma unroll
        for (int rr = 0; rr < 4; rr++) {
            int r = r0 + rr * 16;
            float4 v = *(const float4*)&Qb[(size_t)r * DM + d4];
            qst[(d4 + 0) * APAD + r] = v.x;
            qst[(d4 + 1) * APAD + r] = v.y;
            qst[(d4 + 2) * APAD + r] = v.z;
            qst[(d4 + 3) * APAD + r] = v.w;
        }
    }

    for (int kt = 0; kt <= qt; kt++) {
        __syncthreads();   // protect kps/vs reuse from previous iteration
        const float* Kb = K + ((size_t)(b * SS) + kt * AT) * DM + h * HDIM;
        const float* Vb = V + ((size_t)(b * SS) + kt * AT) * DM + h * HDIM;
        {
            int d4 = (tid & 15) * 4;
            int r0 = tid >> 4;
#pragma unroll
            for (int rr = 0; rr < 4; rr++) {
                int r = r0 + rr * 16;
                float4 kv = *(const float4*)&Kb[(size_t)r * DM + d4];
                kps[(d4 + 0) * APAD + r] = kv.x;
                kps[(d4 + 1) * APAD + r] = kv.y;
                kps[(d4 + 2) * APAD + r] = kv.z;
                kps[(d4 + 3) * APAD + r] = kv.w;
                float4 vv = *(const float4*)&Vb[(size_t)r * DM + d4];
                *(float4*)&vs[r * APAD + d4] = vv;
            }
        }
        __syncthreads();

        // Scores: s[i][j] = sum_d qT[d][4ty+i] * kT[d][4tx+j]
        float s[4][4];
#pragma unroll
        for (int i = 0; i < 4; i++)
#pragma unroll
            for (int j = 0; j < 4; j++) s[i][j] = 0.0f;

#pragma unroll 8
        for (int d = 0; d < AT; d++) {
            float4 a  = *(float4*)&qst[d * APAD + ty * 4];
            float4 bb = *(float4*)&kps[d * APAD + tx * 4];
            float av[4] = {a.x, a.y, a.z, a.w};
            float bv[4] = {bb.x, bb.y, bb.z, bb.w};
#pragma unroll
            for (int i = 0; i < 4; i++)
#pragma unroll
                for (int j = 0; j < 4; j++)
                    s[i][j] = fmaf(av[i], bv[j], s[i][j]);
        }
        __syncthreads();   // everyone done reading kps; it becomes p-buffer

        const bool diag = (kt == qt);
#pragma unroll
        for (int i = 0; i < 4; i++) {
#pragma unroll
            for (int j = 0; j < 4; j++) {
                float sv = s[i][j] * scale;
                if (diag && (tx * 4 + j) > (ty * 4 + i)) sv = NEG;
                s[i][j] = sv;
            }
        }

        // Online softmax per row (reduce across the 16 tx lanes)
#pragma unroll
        for (int i = 0; i < 4; i++) {
            float rmax = fmaxf(fmaxf(s[i][0], s[i][1]), fmaxf(s[i][2], s[i][3]));
#pragma unroll
            for (int msk = 1; msk < 16; msk <<= 1)
                rmax = fmaxf(rmax, __shfl_xor_sync(0xffffffffu, rmax, msk));
            float mn   = fmaxf(mrow[i], rmax);
            float corr = __expf(mrow[i] - mn);
            float rsum = 0.0f;
#pragma unroll
            for (int j = 0; j < 4; j++) {
                s[i][j] = __expf(s[i][j] - mn);
                rsum += s[i][j];
            }
#pragma unroll
            for (int msk = 1; msk < 16; msk <<= 1)
                rsum += __shfl_xor_sync(0xffffffffu, rsum, msk);
            lrow[i] = lrow[i] * corr + rsum;
            mrow[i] = mn;
#pragma unroll
            for (int j = 0; j < 4; j++) o[i][j] *= corr;
            // store p row-major: p[r][c]
            *(float4*)&kps[(ty * 4 + i) * APAD + tx * 4] =
                make_float4(s[i][0], s[i][1], s[i][2], s[i][3]);
        }
        __syncthreads();

        // o[i][j] += sum_c p[4ty+i][c] * v[c][4tx+j]
#pragma unroll 8
        for (int c = 0; c < AT; c++) {
            float4 bv = *(float4*)&vs[c * APAD + tx * 4];
            float bvv[4] = {bv.x, bv.y, bv.z, bv.w};
#pragma unroll
            for (int i = 0; i < 4; i++) {
                float av = kps[(ty * 4 + i) * APAD + c];
#pragma unroll
                for (int j = 0; j < 4; j++)
                    o[i][j] = fmaf(av, bvv[j], o[i][j]);
            }
        }
    }

    // Epilogue: divide by l, write [B,S,D] with head-major packing
    float* Ob = O + ((size_t)(b * SS) + qt * AT) * DM + h * HDIM;
#pragma unroll
    for (int i = 0; i < 4; i++) {
        float inv = 1.0f / lrow[i];
#pragma unroll
        for (int j = 0; j < 4; j++)
            Ob[(size_t)(ty * 4 + i) * DM + tx * 4 + j] = o[i][j] * inv;
    }
}

// ---------------------------------------------------------------------------
// kernel_launch
// inputs: 0 qx, 1 kx, 2 vx, 3 mask(int32, ignored: causal known),
//         4 Wq, 5 bq, 6 Wk, 7 bk, 8 Wv, 9 bv
// ---------------------------------------------------------------------------
extern "C" void kernel_launch(void* const* d_in, const int* in_sizes, int n_in,
                              void* d_out, int out_size)
{
    const float* qx = (const float*)d_in[0];
    const float* kx = (const float*)d_in[1];
    const float* vx = (const float*)d_in[2];
    const float* Wq = (const float*)d_in[4];
    const float* bq = (const float*)d_in[5];
    const float* Wk = (const float*)d_in[6];
    const float* bk = (const float*)d_in[7];
    const float* Wv = (const float*)d_in[8];
    const float* bv = (const float*)d_in[9];
    float* out = (float*)d_out;

    float *gq, *gk, *gv;
    cudaGetSymbolAddress((void**)&gq, g_q);
    cudaGetSymbolAddress((void**)&gk, g_k);
    cudaGetSymbolAddress((void**)&gv, g_v);

    const int M = BB * SS;   // 4096
    const int N = DM;        // 1024
    const int K = DM;        // 1024

    dim3 ggrid(N / BN, M / BM);   // (16, 32)
    gemm_tf32_nt_bias<<<ggrid, 256>>>(qx, Wq, bq, gq, M, N, K);
    gemm_tf32_nt_bias<<<ggrid, 256>>>(kx, Wk, bk, gk, M, N, K);
    gemm_tf32_nt_bias<<<ggrid, 256>>>(vx, Wv, bv, gv, M, N, K);

    cudaFuncSetAttribute(flash_attn_kernel,
                         cudaFuncAttributeMaxDynamicSharedMemorySize, ATT_SMEM);
    dim3 agrid(SS / AT, NH, BB);    // (32, 16, 2)
    flash_attn_kernel<<<agrid, 256, ATT_SMEM>>>(gq, gk, gv, out);
}

// round 5
// speedup vs baseline: 1.9386x; 1.7128x over previous
#include <cuda_runtime.h>
#include <math.h>
#include <stdint.h>

// Problem constants
#define BB   2
#define SS   2048
#define DM   1024
#define NH   16
#define HDIM 64

// Scratch (device globals: allocation-free)
__device__ float g_q[BB * SS * DM];
__device__ float g_k[BB * SS * DM];
__device__ float g_vt[BB * NH * HDIM * SS];   // V transposed: [b][h][d][s]

// ---------------------------------------------------------------------------
// Common helpers
// ---------------------------------------------------------------------------
__device__ __forceinline__ void tf32_split(float x, uint32_t& hi, uint32_t& lo) {
    uint32_t xh = __float_as_uint(x) & 0xFFFFE000u;
    hi = xh;
    lo = __float_as_uint(x - __uint_as_float(xh));
}

__device__ __forceinline__ uint32_t cvt_tf32(float x) {
    uint32_t u;
    asm("cvt.rna.tf32.f32 %0, %1;" : "=r"(u) : "f"(x));
    return u;
}

__device__ __forceinline__ void mma_tf32(float* c,
                                         uint32_t a0, uint32_t a1, uint32_t a2, uint32_t a3,
                                         uint32_t b0, uint32_t b1) {
    asm volatile(
        "mma.sync.aligned.m16n8k8.row.col.f32.tf32.tf32.f32 "
        "{%0,%1,%2,%3}, {%4,%5,%6,%7}, {%8,%9}, {%0,%1,%2,%3};\n"
        : "+f"(c[0]), "+f"(c[1]), "+f"(c[2]), "+f"(c[3])
        : "r"(a0), "r"(a1), "r"(a2), "r"(a3), "r"(b0), "r"(b1));
}

// ---------------------------------------------------------------------------
// GEMM NT with bias, TF32. Two variants:
//  - 1-pass (Q, K projections; logit error budget allows it)
//  - 3-pass (V projection) with TRANSPOSED epilogue writing g_vt[b][h][d][s]
// CTA tile 128x64, BK=16, 256 threads, warp 32x32.
// ---------------------------------------------------------------------------
#define BM 128
#define BN 64
#define BK 16
#define KPAD 4

__global__ __launch_bounds__(256) void gemm_tf32_1p_bias(
    const float* __restrict__ X, const float* __restrict__ W,
    const float* __restrict__ bias, float* __restrict__ Y,
    int M, int N, int K)
{
    __shared__ __align__(16) float As[BM][BK + KPAD];
    __shared__ __align__(16) float Bs[BN][BK + KPAD];

    const int tid  = threadIdx.x;
    const int warp = tid >> 5;
    const int lane = tid & 31;
    const int wm = (warp >> 1) * 32;
    const int wn = (warp & 1) * 32;
    const int g  = lane >> 2;
    const int tg = lane & 3;
    const int m0 = blockIdx.y * BM;
    const int n0 = blockIdx.x * BN;

    float c[2][4][4];
#pragma unroll
    for (int mt = 0; mt < 2; mt++)
#pragma unroll
        for (int nt = 0; nt < 4; nt++)
#pragma unroll
            for (int r = 0; r < 4; r++) c[mt][nt][r] = 0.0f;

    for (int k0 = 0; k0 < K; k0 += BK) {
#pragma unroll
        for (int i = 0; i < 2; i++) {
            int f   = tid + i * 256;
            int row = f >> 2;
            int kq  = (f & 3) * 4;
            *(float4*)&As[row][kq] = *(const float4*)&X[(size_t)(m0 + row) * K + k0 + kq];
        }
        {
            int row = tid >> 2;
            int kq  = (tid & 3) * 4;
            *(float4*)&Bs[row][kq] = *(const float4*)&W[(size_t)(n0 + row) * K + k0 + kq];
        }
        __syncthreads();

#pragma unroll
        for (int ks = 0; ks < 2; ks++) {
            const int kb = ks * 8;
            uint32_t a[2][4];
#pragma unroll
            for (int mt = 0; mt < 2; mt++) {
                int r0 = wm + mt * 16;
                a[mt][0] = cvt_tf32(As[r0 + g    ][kb + tg    ]);
                a[mt][1] = cvt_tf32(As[r0 + g + 8][kb + tg    ]);
                a[mt][2] = cvt_tf32(As[r0 + g    ][kb + tg + 4]);
                a[mt][3] = cvt_tf32(As[r0 + g + 8][kb + tg + 4]);
            }
#pragma unroll
            for (int nt = 0; nt < 4; nt++) {
                int nr = wn + nt * 8 + g;
                uint32_t b0 = cvt_tf32(Bs[nr][kb + tg    ]);
                uint32_t b1 = cvt_tf32(Bs[nr][kb + tg + 4]);
#pragma unroll
                for (int mt = 0; mt < 2; mt++)
                    mma_tf32(c[mt][nt], a[mt][0], a[mt][1], a[mt][2], a[mt][3], b0, b1);
            }
        }
        __syncthreads();
    }

#pragma unroll
    for (int mt = 0; mt < 2; mt++) {
#pragma unroll
        for (int nt = 0; nt < 4; nt++) {
            int m = m0 + wm + mt * 16 + g;
            int n = n0 + wn + nt * 8 + tg * 2;
            float b0 = bias[n];
            float b1 = bias[n + 1];
            *(float2*)&Y[(size_t)m * N + n] =
                make_float2(c[mt][nt][0] + b0, c[mt][nt][1] + b1);
            *(float2*)&Y[(size_t)(m + 8) * N + n] =
                make_float2(c[mt][nt][2] + b0, c[mt][nt][3] + b1);
        }
    }
}

// 3-pass accurate GEMM, transposed output into g_vt[b][h][d][s]
__global__ __launch_bounds__(256) void gemm_tf32_3p_bias_vt(
    const float* __restrict__ X, const float* __restrict__ W,
    const float* __restrict__ bias, float* __restrict__ VT,
    int M, int N, int K)
{
    __shared__ __align__(16) float As[BM][BK + KPAD];
    __shared__ __align__(16) float Bs[BN][BK + KPAD];

    const int tid  = threadIdx.x;
    const int warp = tid >> 5;
    const int lane = tid & 31;
    const int wm = (warp >> 1) * 32;
    const int wn = (warp & 1) * 32;
    const int g  = lane >> 2;
    const int tg = lane & 3;
    const int m0 = blockIdx.y * BM;
    const int n0 = blockIdx.x * BN;

    float c[2][4][4];
#pragma unroll
    for (int mt = 0; mt < 2; mt++)
#pragma unroll
        for (int nt = 0; nt < 4; nt++)
#pragma unroll
            for (int r = 0; r < 4; r++) c[mt][nt][r] = 0.0f;

    for (int k0 = 0; k0 < K; k0 += BK) {
#pragma unroll
        for (int i = 0; i < 2; i++) {
            int f   = tid + i * 256;
            int row = f >> 2;
            int kq  = (f & 3) * 4;
            *(float4*)&As[row][kq] = *(const float4*)&X[(size_t)(m0 + row) * K + k0 + kq];
        }
        {
            int row = tid >> 2;
            int kq  = (tid & 3) * 4;
            *(float4*)&Bs[row][kq] = *(const float4*)&W[(size_t)(n0 + row) * K + k0 + kq];
        }
        __syncthreads();

#pragma unroll
        for (int ks = 0; ks < 2; ks++) {
            const int kb = ks * 8;
            uint32_t ahi[2][4], alo[2][4];
#pragma unroll
            for (int mt = 0; mt < 2; mt++) {
                int r0 = wm + mt * 16;
                tf32_split(As[r0 + g    ][kb + tg    ], ahi[mt][0], alo[mt][0]);
                tf32_split(As[r0 + g + 8][kb + tg    ], ahi[mt][1], alo[mt][1]);
                tf32_split(As[r0 + g    ][kb + tg + 4], ahi[mt][2], alo[mt][2]);
                tf32_split(As[r0 + g + 8][kb + tg + 4], ahi[mt][3], alo[mt][3]);
            }
#pragma unroll
            for (int nt = 0; nt < 4; nt++) {
                int nr = wn + nt * 8 + g;
                uint32_t bh0, bl0, bh1, bl1;
                tf32_split(Bs[nr][kb + tg    ], bh0, bl0);
                tf32_split(Bs[nr][kb + tg + 4], bh1, bl1);
#pragma unroll
                for (int mt = 0; mt < 2; mt++) {
                    mma_tf32(c[mt][nt], ahi[mt][0], ahi[mt][1], ahi[mt][2], ahi[mt][3], bh0, bh1);
                    mma_tf32(c[mt][nt], ahi[mt][0], ahi[mt][1], ahi[mt][2], ahi[mt][3], bl0, bl1);
                    mma_tf32(c[mt][nt], alo[mt][0], alo[mt][1], alo[mt][2], alo[mt][3], bh0, bh1);
                }
            }
        }
        __syncthreads();
    }

    // Transposed epilogue: m=(b,s), n=(h,d) -> VT[((b*NH+h)*HDIM+d)*SS + s]
#pragma unroll
    for (int mt = 0; mt < 2; mt++) {
#pragma unroll
        for (int nt = 0; nt < 4; nt++) {
            int m = m0 + wm + mt * 16 + g;
            int n = n0 + wn + nt * 8 + tg * 2;
            float b0 = bias[n];
            float b1 = bias[n + 1];
            int bidx = m >> 11, s = m & 2047;
#pragma unroll
            for (int e = 0; e < 2; e++) {
                int nn = n + e;
                int hh = nn >> 6, dd = nn & 63;
                size_t base = (((size_t)(bidx * NH + hh)) * HDIM + dd) * SS;
                float bb = e ? b1 : b0;
                VT[base + s]     = c[mt][nt][e]     + bb;
                VT[base + s + 8] = c[mt][nt][e + 2] + bb;
            }
        }
    }
}

// ---------------------------------------------------------------------------
// Tensor-core flash attention (TF32), causal.
// CTA: 128 q-rows of one (b,h); 4 warps x 32 rows; k-tiles of 64.
// QK^T: single-pass tf32 (logits tiny -> abs err ~6e-5).
// P*V: 3-pass split tf32 (~1e-6).
// Q frags in registers; P via warp-private smem roundtrip; V pre-transposed.
// ---------------------------------------------------------------------------
#define QT 128
#define KT 64
#define PSTR 68
#define FA_SMEM ((128 * PSTR + 64 * PSTR + 4 * 32 * PSTR) * (int)sizeof(float))

__global__ __launch_bounds__(128) void flash_attn_tc(
    const float* __restrict__ Q, const float* __restrict__ K,
    const float* __restrict__ VT, float* __restrict__ O)
{
    extern __shared__ float sm[];
    float* sK = sm;                       // Q tile [128][PSTR] first, then K tile [64][PSTR]
    float* sV = sm + 128 * PSTR;          // VT tile [64][PSTR]  (rows = d, cols = key)
    float* sP = sm + (128 + 64) * PSTR;   // per-warp P [32][PSTR]

    const int tid  = threadIdx.x;
    const int w    = tid >> 5;
    const int lane = tid & 31;
    const int g    = lane >> 2;
    const int tg   = lane & 3;
    const int qt   = (int)gridDim.x - 1 - (int)blockIdx.x;  // heavy tiles first
    const int h    = blockIdx.y;
    const int b    = blockIdx.z;
    const int qbase = qt * QT;
    const float NEG = -1.0e30f;

    // ---- Load Q tile (pre-scaled by 1/32, exact power of 2) and extract frags
    const float* Qg = Q + ((size_t)(b * SS) + qbase) * DM + h * HDIM;
#pragma unroll
    for (int i = 0; i < 16; i++) {
        int f = tid + i * 128;
        int row = f >> 4, c4 = (f & 15) * 4;
        *(float4*)&sK[row * PSTR + c4] = *(const float4*)&Qg[(size_t)row * DM + c4];
    }
    __syncthreads();

    uint32_t qf[2][8][4];
#pragma unroll
    for (int mt = 0; mt < 2; mt++) {
        int r0 = w * 32 + mt * 16 + g;
#pragma unroll
        for (int ks = 0; ks < 8; ks++) {
            int cc = ks * 8 + tg;
            qf[mt][ks][0] = cvt_tf32(sK[(r0    ) * PSTR + cc    ] * 0.03125f);
            qf[mt][ks][1] = cvt_tf32(sK[(r0 + 8) * PSTR + cc    ] * 0.03125f);
            qf[mt][ks][2] = cvt_tf32(sK[(r0    ) * PSTR + cc + 4] * 0.03125f);
            qf[mt][ks][3] = cvt_tf32(sK[(r0 + 8) * PSTR + cc + 4] * 0.03125f);
        }
    }

    float of[2][8][4];
    float mrow[2][2], lrow[2][2];
#pragma unroll
    for (int mt = 0; mt < 2; mt++) {
        mrow[mt][0] = NEG; mrow[mt][1] = NEG;
        lrow[mt][0] = 0.f; lrow[mt][1] = 0.f;
#pragma unroll
        for (int nt = 0; nt < 8; nt++)
#pragma unroll
            for (int r = 0; r < 4; r++) of[mt][nt][r] = 0.f;
    }

    float* Pw = sP + w * 32 * PSTR;
    const int nkt = 2 * qt + 2;

    for (int kt = 0; kt < nkt; kt++) {
        __syncthreads();   // previous iteration done reading tiles
        // Load K tile [64 keys][64 d]
        const float* Kg = K + ((size_t)(b * SS) + kt * KT) * DM + h * HDIM;
        const float* Vg = VT + ((size_t)(b * NH + h) * HDIM) * SS + kt * KT;
#pragma unroll
        for (int i = 0; i < 8; i++) {
            int f = tid + i * 128;
            int row = f >> 4, c4 = (f & 15) * 4;
            *(float4*)&sK[row * PSTR + c4] = *(const float4*)&Kg[(size_t)row * DM + c4];
            *(float4*)&sV[row * PSTR + c4] = *(const float4*)&Vg[(size_t)row * SS + c4];
        }
        __syncthreads();

        // Warps whose rows are all below every key in this tile: skip compute
        if (kt * KT > qbase + w * 32 + 31) continue;

        // ---- S = Q K^T (single-pass tf32)
        float s[2][8][4];
#pragma unroll
        for (int mt = 0; mt < 2; mt++)
#pragma unroll
            for (int nt = 0; nt < 8; nt++)
#pragma unroll
                for (int r = 0; r < 4; r++) s[mt][nt][r] = 0.f;

#pragma unroll
        for (int ks = 0; ks < 8; ks++) {
#pragma unroll
            for (int nt = 0; nt < 8; nt++) {
                int nr = nt * 8 + g;
                uint32_t b0 = cvt_tf32(sK[nr * PSTR + ks * 8 + tg    ]);
                uint32_t b1 = cvt_tf32(sK[nr * PSTR + ks * 8 + tg + 4]);
                mma_tf32(s[0][nt], qf[0][ks][0], qf[0][ks][1], qf[0][ks][2], qf[0][ks][3], b0, b1);
                mma_tf32(s[1][nt], qf[1][ks][0], qf[1][ks][1], qf[1][ks][2], qf[1][ks][3], b0, b1);
            }
        }

        // ---- causal mask (only the last two k-tiles can cross the diagonal)
        if (kt >= 2 * qt) {
#pragma unroll
            for (int mt = 0; mt < 2; mt++) {
                int row0 = qbase + w * 32 + mt * 16 + g;
#pragma unroll
                for (int nt = 0; nt < 8; nt++) {
                    int col = kt * KT + nt * 8 + 2 * tg;
                    if (col     > row0    ) s[mt][nt][0] = NEG;
                    if (col + 1 > row0    ) s[mt][nt][1] = NEG;
                    if (col     > row0 + 8) s[mt][nt][2] = NEG;
                    if (col + 1 > row0 + 8) s[mt][nt][3] = NEG;
                }
            }
        }

        // ---- online softmax + store P (warp-private)
#pragma unroll
        for (int mt = 0; mt < 2; mt++) {
            float rm0 = NEG, rm1 = NEG;
#pragma unroll
            for (int nt = 0; nt < 8; nt++) {
                rm0 = fmaxf(rm0, fmaxf(s[mt][nt][0], s[mt][nt][1]));
                rm1 = fmaxf(rm1, fmaxf(s[mt][nt][2], s[mt][nt][3]));
            }
#pragma unroll
            for (int d = 1; d < 4; d <<= 1) {
                rm0 = fmaxf(rm0, __shfl_xor_sync(0xffffffffu, rm0, d));
                rm1 = fmaxf(rm1, __shfl_xor_sync(0xffffffffu, rm1, d));
            }
            float mn0 = fmaxf(mrow[mt][0], rm0);
            float mn1 = fmaxf(mrow[mt][1], rm1);
            float corr0 = __expf(mrow[mt][0] - mn0);
            float corr1 = __expf(mrow[mt][1] - mn1);
            float rs0 = 0.f, rs1 = 0.f;
#pragma unroll
            for (int nt = 0; nt < 8; nt++) {
                s[mt][nt][0] = __expf(s[mt][nt][0] - mn0);
                s[mt][nt][1] = __expf(s[mt][nt][1] - mn0);
                s[mt][nt][2] = __expf(s[mt][nt][2] - mn1);
                s[mt][nt][3] = __expf(s[mt][nt][3] - mn1);
                rs0 += s[mt][nt][0] + s[mt][nt][1];
                rs1 += s[mt][nt][2] + s[mt][nt][3];
            }
#pragma unroll
            for (int d = 1; d < 4; d <<= 1) {
                rs0 += __shfl_xor_sync(0xffffffffu, rs0, d);
                rs1 += __shfl_xor_sync(0xffffffffu, rs1, d);
            }
            lrow[mt][0] = lrow[mt][0] * corr0 + rs0;
            lrow[mt][1] = lrow[mt][1] * corr1 + rs1;
            mrow[mt][0] = mn0;
            mrow[mt][1] = mn1;
#pragma unroll
            for (int nt = 0; nt < 8; nt++) {
                of[mt][nt][0] *= corr0;
                of[mt][nt][1] *= corr0;
                of[mt][nt][2] *= corr1;
                of[mt][nt][3] *= corr1;
            }
            int pr = mt * 16 + g;
#pragma unroll
            for (int nt = 0; nt < 8; nt++) {
                *(float2*)&Pw[(pr    ) * PSTR + nt * 8 + 2 * tg] =
                    make_float2(s[mt][nt][0], s[mt][nt][1]);
                *(float2*)&Pw[(pr + 8) * PSTR + nt * 8 + 2 * tg] =
                    make_float2(s[mt][nt][2], s[mt][nt][3]);
            }
        }
        __syncwarp();

        // ---- O += P V  (3-pass split tf32)
#pragma unroll
        for (int ks = 0; ks < 8; ks++) {
            uint32_t ah[2][4], al[2][4];
#pragma unroll
            for (int mt = 0; mt < 2; mt++) {
                int pr = mt * 16 + g;
                int cc = ks * 8 + tg;
                tf32_split(Pw[(pr    ) * PSTR + cc    ], ah[mt][0], al[mt][0]);
                tf32_split(Pw[(pr + 8) * PSTR + cc    ], ah[mt][1], al[mt][1]);
                tf32_split(Pw[(pr    ) * PSTR + cc + 4], ah[mt][2], al[mt][2]);
                tf32_split(Pw[(pr + 8) * PSTR + cc + 4], ah[mt][3], al[mt][3]);
            }
#pragma unroll
            for (int nt = 0; nt < 8; nt++) {
                int nr = nt * 8 + g;
                uint32_t bh0, bl0, bh1, bl1;
                tf32_split(sV[nr * PSTR + ks * 8 + tg    ], bh0, bl0);
                tf32_split(sV[nr * PSTR + ks * 8 + tg + 4], bh1, bl1);
#pragma unroll
                for (int mt = 0; mt < 2; mt++) {
                    mma_tf32(of[mt][nt], ah[mt][0], ah[mt][1], ah[mt][2], ah[mt][3], bh0, bh1);
                    mma_tf32(of[mt][nt], ah[mt][0], ah[mt][1], ah[mt][2], ah[mt][3], bl0, bl1);
                    mma_tf32(of[mt][nt], al[mt][0], al[mt][1], al[mt][2], al[mt][3], bh0, bh1);
                }
            }
        }
        __syncwarp();
    }

    // ---- epilogue: O /= l, write [b][s][h*64+d]
    float* Og = O + ((size_t)(b * SS) + qbase) * DM + h * HDIM;
#pragma unroll
    for (int mt = 0; mt < 2; mt++) {
        float inv0 = 1.0f / lrow[mt][0];
        float inv1 = 1.0f / lrow[mt][1];
        int r0 = w * 32 + mt * 16 + g;
#pragma unroll
        for (int nt = 0; nt < 8; nt++) {
            int cc = nt * 8 + 2 * tg;
            *(float2*)&Og[(size_t)(r0    ) * DM + cc] =
                make_float2(of[mt][nt][0] * inv0, of[mt][nt][1] * inv0);
            *(float2*)&Og[(size_t)(r0 + 8) * DM + cc] =
                make_float2(of[mt][nt][2] * inv1, of[mt][nt][3] * inv1);
        }
    }
}

// ---------------------------------------------------------------------------
// kernel_launch
// ---------------------------------------------------------------------------
extern "C" void kernel_launch(void* const* d_in, const int* in_sizes, int n_in,
                              void* d_out, int out_size)
{
    const float* qx = (const float*)d_in[0];
    const float* kx = (const float*)d_in[1];
    const float* vx = (const float*)d_in[2];
    const float* Wq = (const float*)d_in[4];
    const float* bq = (const float*)d_in[5];
    const float* Wk = (const float*)d_in[6];
    const float* bk = (const float*)d_in[7];
    const float* Wv = (const float*)d_in[8];
    const float* bv = (const float*)d_in[9];
    float* out = (float*)d_out;

    float *gq, *gk, *gvt;
    cudaGetSymbolAddress((void**)&gq, g_q);
    cudaGetSymbolAddress((void**)&gk, g_k);
    cudaGetSymbolAddress((void**)&gvt, g_vt);

    const int M = BB * SS;   // 4096
    const int N = DM;        // 1024
    const int K = DM;        // 1024

    dim3 ggrid(N / BN, M / BM);   // (16, 32)
    gemm_tf32_1p_bias<<<ggrid, 256>>>(qx, Wq, bq, gq, M, N, K);
    gemm_tf32_1p_bias<<<ggrid, 256>>>(kx, Wk, bk, gk, M, N, K);
    gemm_tf32_3p_bias_vt<<<ggrid, 256>>>(vx, Wv, bv, gvt, M, N, K);

    cudaFuncSetAttribute(flash_attn_tc,
                         cudaFuncAttributeMaxDynamicSharedMemorySize, FA_SMEM);
    dim3 agrid(SS / QT, NH, BB);    // (16, 16, 2)
    flash_attn_tc<<<agrid, 128, FA_SMEM>>>(gq, gk, gvt, out);
}

// round 6
// speedup vs baseline: 2.0961x; 1.0812x over previous
#include <cuda_runtime.h>
#include <math.h>
#include <stdint.h>

// Problem constants
#define BB   2
#define SS   2048
#define DM   1024
#define NH   16
#define HDIM 64

// Scratch (device globals: allocation-free)
// Q, K stored as tf32 bit patterns (Q pre-scaled by 1/32).
// V stored transposed [b][h][d][s], pre-split into tf32 hi + tf32 lo.
__device__ uint32_t g_qt[BB * SS * DM];
__device__ uint32_t g_kt[BB * SS * DM];
__device__ uint32_t g_vthi[BB * NH * HDIM * SS];
__device__ uint32_t g_vtlo[BB * NH * HDIM * SS];

// ---------------------------------------------------------------------------
// Helpers
// ---------------------------------------------------------------------------
__device__ __forceinline__ void tf32_split(float x, uint32_t& hi, uint32_t& lo) {
    uint32_t xh = __float_as_uint(x) & 0xFFFFE000u;
    hi = xh;
    lo = __float_as_uint(x - __uint_as_float(xh));
}

__device__ __forceinline__ uint32_t cvt_tf32(float x) {
    uint32_t u;
    asm("cvt.rna.tf32.f32 %0, %1;" : "=r"(u) : "f"(x));
    return u;
}

__device__ __forceinline__ void mma_tf32(float* c,
                                         uint32_t a0, uint32_t a1, uint32_t a2, uint32_t a3,
                                         uint32_t b0, uint32_t b1) {
    asm volatile(
        "mma.sync.aligned.m16n8k8.row.col.f32.tf32.tf32.f32 "
        "{%0,%1,%2,%3}, {%4,%5,%6,%7}, {%8,%9}, {%0,%1,%2,%3};\n"
        : "+f"(c[0]), "+f"(c[1]), "+f"(c[2]), "+f"(c[3])
        : "r"(a0), "r"(a1), "r"(a2), "r"(a3), "r"(b0), "r"(b1));
}

// ---------------------------------------------------------------------------
// Projection GEMMs. CTA tile 128x64, BK=16, 256 threads, warp 32x32.
//  - 1-pass (Q, K): epilogue writes tf32 bit pattern (optionally scaled).
//  - 3-pass (V): epilogue writes transposed, pre-split hi/lo tf32.
// ---------------------------------------------------------------------------
#define BM 128
#define BN 64
#define BK 16
#define KPAD 4

__global__ __launch_bounds__(256) void gemm_tf32_1p_tf32out(
    const float* __restrict__ X, const float* __restrict__ W,
    const float* __restrict__ bias, uint32_t* __restrict__ Y,
    int M, int N, int K, float oscale)
{
    __shared__ __align__(16) float As[BM][BK + KPAD];
    __shared__ __align__(16) float Bs[BN][BK + KPAD];

    const int tid  = threadIdx.x;
    const int warp = tid >> 5;
    const int lane = tid & 31;
    const int wm = (warp >> 1) * 32;
    const int wn = (warp & 1) * 32;
    const int g  = lane >> 2;
    const int tg = lane & 3;
    const int m0 = blockIdx.y * BM;
    const int n0 = blockIdx.x * BN;

    float c[2][4][4];
#pragma unroll
    for (int mt = 0; mt < 2; mt++)
#pragma unroll
        for (int nt = 0; nt < 4; nt++)
#pragma unroll
            for (int r = 0; r < 4; r++) c[mt][nt][r] = 0.0f;

    for (int k0 = 0; k0 < K; k0 += BK) {
#pragma unroll
        for (int i = 0; i < 2; i++) {
            int f   = tid + i * 256;
            int row = f >> 2;
            int kq  = (f & 3) * 4;
            *(float4*)&As[row][kq] = *(const float4*)&X[(size_t)(m0 + row) * K + k0 + kq];
        }
        {
            int row = tid >> 2;
            int kq  = (tid & 3) * 4;
            *(float4*)&Bs[row][kq] = *(const float4*)&W[(size_t)(n0 + row) * K + k0 + kq];
        }
        __syncthreads();

#pragma unroll
        for (int ks = 0; ks < 2; ks++) {
            const int kb = ks * 8;
            uint32_t a[2][4];
#pragma unroll
            for (int mt = 0; mt < 2; mt++) {
                int r0 = wm + mt * 16;
                a[mt][0] = cvt_tf32(As[r0 + g    ][kb + tg    ]);
                a[mt][1] = cvt_tf32(As[r0 + g + 8][kb + tg    ]);
                a[mt][2] = cvt_tf32(As[r0 + g    ][kb + tg + 4]);
                a[mt][3] = cvt_tf32(As[r0 + g + 8][kb + tg + 4]);
            }
#pragma unroll
            for (int nt = 0; nt < 4; nt++) {
                int nr = wn + nt * 8 + g;
                uint32_t b0 = cvt_tf32(Bs[nr][kb + tg    ]);
                uint32_t b1 = cvt_tf32(Bs[nr][kb + tg + 4]);
#pragma unroll
                for (int mt = 0; mt < 2; mt++)
                    mma_tf32(c[mt][nt], a[mt][0], a[mt][1], a[mt][2], a[mt][3], b0, b1);
            }
        }
        __syncthreads();
    }

#pragma unroll
    for (int mt = 0; mt < 2; mt++) {
#pragma unroll
        for (int nt = 0; nt < 4; nt++) {
            int m = m0 + wm + mt * 16 + g;
            int n = n0 + wn + nt * 8 + tg * 2;
            float b0 = bias[n];
            float b1 = bias[n + 1];
            Y[(size_t)m * N + n]           = cvt_tf32((c[mt][nt][0] + b0) * oscale);
            Y[(size_t)m * N + n + 1]       = cvt_tf32((c[mt][nt][1] + b1) * oscale);
            Y[(size_t)(m + 8) * N + n]     = cvt_tf32((c[mt][nt][2] + b0) * oscale);
            Y[(size_t)(m + 8) * N + n + 1] = cvt_tf32((c[mt][nt][3] + b1) * oscale);
        }
    }
}

// 3-pass accurate GEMM, transposed + pre-split epilogue into hi/lo tf32 arrays
__global__ __launch_bounds__(256) void gemm_tf32_3p_vt_split(
    const float* __restrict__ X, const float* __restrict__ W,
    const float* __restrict__ bias,
    uint32_t* __restrict__ VTHI, uint32_t* __restrict__ VTLO,
    int M, int N, int K)
{
    __shared__ __align__(16) float As[BM][BK + KPAD];
    __shared__ __align__(16) float Bs[BN][BK + KPAD];

    const int tid  = threadIdx.x;
    const int warp = tid >> 5;
    const int lane = tid & 31;
    const int wm = (warp >> 1) * 32;
    const int wn = (warp & 1) * 32;
    const int g  = lane >> 2;
    const int tg = lane & 3;
    const int m0 = blockIdx.y * BM;
    const int n0 = blockIdx.x * BN;

    float c[2][4][4];
#pragma unroll
    for (int mt = 0; mt < 2; mt++)
#pragma unroll
        for (int nt = 0; nt < 4; nt++)
#pragma unroll
            for (int r = 0; r < 4; r++) c[mt][nt][r] = 0.0f;

    for (int k0 = 0; k0 < K; k0 += BK) {
#pragma unroll
        for (int i = 0; i < 2; i++) {
            int f   = tid + i * 256;
            int row = f >> 2;
            int kq  = (f & 3) * 4;
            *(float4*)&As[row][kq] = *(const float4*)&X[(size_t)(m0 + row) * K + k0 + kq];
        }
        {
            int row = tid >> 2;
            int kq  = (tid & 3) * 4;
            *(float4*)&Bs[row][kq] = *(const float4*)&W[(size_t)(n0 + row) * K + k0 + kq];
        }
        __syncthreads();

#pragma unroll
        for (int ks = 0; ks < 2; ks++) {
            const int kb = ks * 8;
            uint32_t ahi[2][4], alo[2][4];
#pragma unroll
            for (int mt = 0; mt < 2; mt++) {
                int r0 = wm + mt * 16;
                tf32_split(As[r0 + g    ][kb + tg    ], ahi[mt][0], alo[mt][0]);
                tf32_split(As[r0 + g + 8][kb + tg    ], ahi[mt][1], alo[mt][1]);
                tf32_split(As[r0 + g    ][kb + tg + 4], ahi[mt][2], alo[mt][2]);
                tf32_split(As[r0 + g + 8][kb + tg + 4], ahi[mt][3], alo[mt][3]);
            }
#pragma unroll
            for (int nt = 0; nt < 4; nt++) {
                int nr = wn + nt * 8 + g;
                uint32_t bh0, bl0, bh1, bl1;
                tf32_split(Bs[nr][kb + tg    ], bh0, bl0);
                tf32_split(Bs[nr][kb + tg + 4], bh1, bl1);
#pragma unroll
                for (int mt = 0; mt < 2; mt++) {
                    mma_tf32(c[mt][nt], ahi[mt][0], ahi[mt][1], ahi[mt][2], ahi[mt][3], bh0, bh1);
                    mma_tf32(c[mt][nt], ahi[mt][0], ahi[mt][1], ahi[mt][2], ahi[mt][3], bl0, bl1);
                    mma_tf32(c[mt][nt], alo[mt][0], alo[mt][1], alo[mt][2], alo[mt][3], bh0, bh1);
                }
            }
        }
        __syncthreads();
    }

    // Transposed + split epilogue: m=(b,s), n=(h,d) -> [((b*NH+h)*HDIM+d)*SS + s]
#pragma unroll
    for (int mt = 0; mt < 2; mt++) {
#pragma unroll
        for (int nt = 0; nt < 4; nt++) {
            int m = m0 + wm + mt * 16 + g;
            int n = n0 + wn + nt * 8 + tg * 2;
            int bidx = m >> 11, s = m & 2047;
#pragma unroll
            for (int e = 0; e < 2; e++) {
                int nn = n + e;
                int hh = nn >> 6, dd = nn & 63;
                size_t base = (((size_t)(bidx * NH + hh)) * HDIM + dd) * SS;
                float bb = bias[nn];
#pragma unroll
                for (int rr = 0; rr < 2; rr++) {
                    float y = c[mt][nt][e + 2 * rr] + bb;
                    uint32_t hi = __float_as_uint(y) & 0xFFFFE000u;  // tf32-exact
                    float lo = y - __uint_as_float(hi);
                    VTHI[base + s + 8 * rr] = hi;
                    VTLO[base + s + 8 * rr] = cvt_tf32(lo);
                }
            }
        }
    }
}

// ---------------------------------------------------------------------------
// Tensor-core flash attention (TF32), causal.
// CTA: 128 q-rows of one (b,h); 4 warps x 32 rows; k-tiles of 64.
// All operands arrive pre-converted tf32 -> zero cvt/split in the main loop.
// QK^T single-pass; P*V 2-pass with pre-split V (V-side exact).
// ---------------------------------------------------------------------------
#define QT 128
#define KT 64
#define PSTR 68
#define FA_SMEM ((3 * 64 * PSTR + 4 * 32 * PSTR) * (int)sizeof(uint32_t))

__global__ __launch_bounds__(128) void flash_attn_tc(
    const uint32_t* __restrict__ Qt, const uint32_t* __restrict__ Kt,
    const uint32_t* __restrict__ VHI, const uint32_t* __restrict__ VLO,
    float* __restrict__ O)
{
    extern __shared__ uint32_t smu[];
    uint32_t* sK  = smu;                  // K tile  [64 keys][PSTR] (cols = d)
    uint32_t* sVh = smu + 64 * PSTR;      // V hi    [64 d][PSTR]    (cols = key)
    uint32_t* sVl = smu + 2 * 64 * PSTR;  // V lo    [64 d][PSTR]
    uint32_t* sP  = smu + 3 * 64 * PSTR;  // per-warp P [32][PSTR] (tf32)

    const int tid  = threadIdx.x;
    const int w    = tid >> 5;
    const int lane = tid & 31;
    const int g    = lane >> 2;
    const int tg   = lane & 3;
    const int qt   = (int)gridDim.x - 1 - (int)blockIdx.x;  // heavy tiles first
    const int h    = blockIdx.y;
    const int b    = blockIdx.z;
    const int qbase = qt * QT;
    const float NEG = -1.0e30f;

    // ---- Q fragments straight from gmem (already tf32 + pre-scaled)
    const uint32_t* Qg = Qt + ((size_t)(b * SS) + qbase) * DM + h * HDIM;
    uint32_t qf[2][8][4];
#pragma unroll
    for (int mt = 0; mt < 2; mt++) {
        int r0 = w * 32 + mt * 16 + g;
#pragma unroll
        for (int ks = 0; ks < 8; ks++) {
            int cc = ks * 8 + tg;
            qf[mt][ks][0] = Qg[(size_t)(r0    ) * DM + cc    ];
            qf[mt][ks][1] = Qg[(size_t)(r0 + 8) * DM + cc    ];
            qf[mt][ks][2] = Qg[(size_t)(r0    ) * DM + cc + 4];
            qf[mt][ks][3] = Qg[(size_t)(r0 + 8) * DM + cc + 4];
        }
    }

    float of[2][8][4];
    float mrow[2][2], lrow[2][2];
#pragma unroll
    for (int mt = 0; mt < 2; mt++) {
        mrow[mt][0] = NEG; mrow[mt][1] = NEG;
        lrow[mt][0] = 0.f; lrow[mt][1] = 0.f;
#pragma unroll
        for (int nt = 0; nt < 8; nt++)
#pragma unroll
            for (int r = 0; r < 4; r++) of[mt][nt][r] = 0.f;
    }

    uint32_t* Pw = sP + w * 32 * PSTR;
    const int nkt = 2 * qt + 2;

    for (int kt = 0; kt < nkt; kt++) {
        __syncthreads();
        const uint32_t* Kg = Kt  + ((size_t)(b * SS) + kt * KT) * DM + h * HDIM;
        size_t vbase = ((size_t)(b * NH + h) * HDIM) * SS + kt * KT;
#pragma unroll
        for (int i = 0; i < 8; i++) {
            int f = tid + i * 128;
            int row = f >> 4, c4 = (f & 15) * 4;
            *(uint4*)&sK[row * PSTR + c4]  = *(const uint4*)&Kg[(size_t)row * DM + c4];
            *(uint4*)&sVh[row * PSTR + c4] = *(const uint4*)&VHI[vbase + (size_t)row * SS + c4];
            *(uint4*)&sVl[row * PSTR + c4] = *(const uint4*)&VLO[vbase + (size_t)row * SS + c4];
        }
        __syncthreads();

        if (kt * KT > qbase + w * 32 + 31) continue;   // fully masked for this warp

        // ---- S = Q K^T (single-pass tf32)
        float s[2][8][4];
#pragma unroll
        for (int mt = 0; mt < 2; mt++)
#pragma unroll
            for (int nt = 0; nt < 8; nt++)
#pragma unroll
                for (int r = 0; r < 4; r++) s[mt][nt][r] = 0.f;

#pragma unroll
        for (int ks = 0; ks < 8; ks++) {
#pragma unroll
            for (int nt = 0; nt < 8; nt++) {
                int nr = nt * 8 + g;
                uint32_t b0 = sK[nr * PSTR + ks * 8 + tg    ];
                uint32_t b1 = sK[nr * PSTR + ks * 8 + tg + 4];
                mma_tf32(s[0][nt], qf[0][ks][0], qf[0][ks][1], qf[0][ks][2], qf[0][ks][3], b0, b1);
                mma_tf32(s[1][nt], qf[1][ks][0], qf[1][ks][1], qf[1][ks][2], qf[1][ks][3], b0, b1);
            }
        }

        // ---- causal mask (only tiles that can cross the diagonal)
        if (kt >= 2 * qt) {
#pragma unroll
            for (int mt = 0; mt < 2; mt++) {
                int row0 = qbase + w * 32 + mt * 16 + g;
#pragma unroll
                for (int nt = 0; nt < 8; nt++) {
                    int col = kt * KT + nt * 8 + 2 * tg;
                    if (col     > row0    ) s[mt][nt][0] = NEG;
                    if (col + 1 > row0    ) s[mt][nt][1] = NEG;
                    if (col     > row0 + 8) s[mt][nt][2] = NEG;
                    if (col + 1 > row0 + 8) s[mt][nt][3] = NEG;
                }
            }
        }

        // ---- online softmax + store P as tf32 (warp-private)
#pragma unroll
        for (int mt = 0; mt < 2; mt++) {
            float rm0 = NEG, rm1 = NEG;
#pragma unroll
            for (int nt = 0; nt < 8; nt++) {
                rm0 = fmaxf(rm0, fmaxf(s[mt][nt][0], s[mt][nt][1]));
                rm1 = fmaxf(rm1, fmaxf(s[mt][nt][2], s[mt][nt][3]));
            }
#pragma unroll
            for (int d = 1; d < 4; d <<= 1) {
                rm0 = fmaxf(rm0, __shfl_xor_sync(0xffffffffu, rm0, d));
                rm1 = fmaxf(rm1, __shfl_xor_sync(0xffffffffu, rm1, d));
            }
            float mn0 = fmaxf(mrow[mt][0], rm0);
            float mn1 = fmaxf(mrow[mt][1], rm1);
            float corr0 = __expf(mrow[mt][0] - mn0);
            float corr1 = __expf(mrow[mt][1] - mn1);
            float rs0 = 0.f, rs1 = 0.f;
#pragma unroll
            for (int nt = 0; nt < 8; nt++) {
                s[mt][nt][0] = __expf(s[mt][nt][0] - mn0);
                s[mt][nt][1] = __expf(s[mt][nt][1] - mn0);
                s[mt][nt][2] = __expf(s[mt][nt][2] - mn1);
                s[mt][nt][3] = __expf(s[mt][nt][3] - mn1);
                rs0 += s[mt][nt][0] + s[mt][nt][1];
                rs1 += s[mt][nt][2] + s[mt][nt][3];
            }
#pragma unroll
            for (int d = 1; d < 4; d <<= 1) {
                rs0 += __shfl_xor_sync(0xffffffffu, rs0, d);
                rs1 += __shfl_xor_sync(0xffffffffu, rs1, d);
            }
            lrow[mt][0] = lrow[mt][0] * corr0 + rs0;
            lrow[mt][1] = lrow[mt][1] * corr1 + rs1;
            mrow[mt][0] = mn0;
            mrow[mt][1] = mn1;
#pragma unroll
            for (int nt = 0; nt < 8; nt++) {
                of[mt][nt][0] *= corr0;
                of[mt][nt][1] *= corr0;
                of[mt][nt][2] *= corr1;
                of[mt][nt][3] *= corr1;
            }
            int pr = mt * 16 + g;
#pragma unroll
            for (int nt = 0; nt < 8; nt++) {
                uint2 p01 = make_uint2(cvt_tf32(s[mt][nt][0]), cvt_tf32(s[mt][nt][1]));
                uint2 p23 = make_uint2(cvt_tf32(s[mt][nt][2]), cvt_tf32(s[mt][nt][3]));
                *(uint2*)&Pw[(pr    ) * PSTR + nt * 8 + 2 * tg] = p01;
                *(uint2*)&Pw[(pr + 8) * PSTR + nt * 8 + 2 * tg] = p23;
            }
        }
        __syncwarp();

        // ---- O += P Vhi + P Vlo (V-side exact)
#pragma unroll
        for (int ks = 0; ks < 8; ks++) {
            uint32_t a[2][4];
#pragma unroll
            for (int mt = 0; mt < 2; mt++) {
                int pr = mt * 16 + g;
                int cc = ks * 8 + tg;
                a[mt][0] = Pw[(pr    ) * PSTR + cc    ];
                a[mt][1] = Pw[(pr + 8) * PSTR + cc    ];
                a[mt][2] = Pw[(pr    ) * PSTR + cc + 4];
                a[mt][3] = Pw[(pr + 8) * PSTR + cc + 4];
            }
#pragma unroll
            for (int nt = 0; nt < 8; nt++) {
                int nr = nt * 8 + g;
                uint32_t bh0 = sVh[nr * PSTR + ks * 8 + tg    ];
                uint32_t bh1 = sVh[nr * PSTR + ks * 8 + tg + 4];
                uint32_t bl0 = sVl[nr * PSTR + ks * 8 + tg    ];
                uint32_t bl1 = sVl[nr * PSTR + ks * 8 + tg + 4];
#pragma unroll
                for (int mt = 0; mt < 2; mt++) {
                    mma_tf32(of[mt][nt], a[mt][0], a[mt][1], a[mt][2], a[mt][3], bh0, bh1);
                    mma_tf32(of[mt][nt], a[mt][0], a[mt][1], a[mt][2], a[mt][3], bl0, bl1);
                }
            }
        }
        __syncwarp();
    }

    // ---- epilogue: O /= l, write [b][s][h*64+d]
    float* Og = O + ((size_t)(b * SS) + qbase) * DM + h * HDIM;
#pragma unroll
    for (int mt = 0; mt < 2; mt++) {
        float inv0 = 1.0f / lrow[mt][0];
        float inv1 = 1.0f / lrow[mt][1];
        int r0 = w * 32 + mt * 16 + g;
#pragma unroll
        for (int nt = 0; nt < 8; nt++) {
            int cc = nt * 8 + 2 * tg;
            *(float2*)&Og[(size_t)(r0    ) * DM + cc] =
                make_float2(of[mt][nt][0] * inv0, of[mt][nt][1] * inv0);
            *(float2*)&Og[(size_t)(r0 + 8) * DM + cc] =
                make_float2(of[mt][nt][2] * inv1, of[mt][nt][3] * inv1);
        }
    }
}

// ---------------------------------------------------------------------------
// kernel_launch
// ---------------------------------------------------------------------------
extern "C" void kernel_launch(void* const* d_in, const int* in_sizes, int n_in,
                              void* d_out, int out_size)
{
    const float* qx = (const float*)d_in[0];
    const float* kx = (const float*)d_in[1];
    const float* vx = (const float*)d_in[2];
    const float* Wq = (const float*)d_in[4];
    const float* bq = (const float*)d_in[5];
    const float* Wk = (const float*)d_in[6];
    const float* bk = (const float*)d_in[7];
    const float* Wv = (const float*)d_in[8];
    const float* bv = (const float*)d_in[9];
    float* out = (float*)d_out;

    uint32_t *gq, *gk, *gvh, *gvl;
    cudaGetSymbolAddress((void**)&gq,  g_qt);
    cudaGetSymbolAddress((void**)&gk,  g_kt);
    cudaGetSymbolAddress((void**)&gvh, g_vthi);
    cudaGetSymbolAddress((void**)&gvl, g_vtlo);

    const int M = BB * SS;   // 4096
    const int N = DM;        // 1024
    const int K = DM;        // 1024

    dim3 ggrid(N / BN, M / BM);   // (16, 32)
    gemm_tf32_1p_tf32out<<<ggrid, 256>>>(qx, Wq, bq, gq, M, N, K, 0.03125f);
    gemm_tf32_1p_tf32out<<<ggrid, 256>>>(kx, Wk, bk, gk, M, N, K, 1.0f);
    gemm_tf32_3p_vt_split<<<ggrid, 256>>>(vx, Wv, bv, gvh, gvl, M, N, K);

    cudaFuncSetAttribute(flash_attn_tc,
                         cudaFuncAttributeMaxDynamicSharedMemorySize, FA_SMEM);
    dim3 agrid(SS / QT, NH, BB);    // (16, 16, 2)
    flash_attn_tc<<<agrid, 128, FA_SMEM>>>(gq, gk, gvh, gvl, out);
}

// round 7
// speedup vs baseline: 2.2323x; 1.0650x over previous
#include <cuda_runtime.h>
#include <math.h>
#include <stdint.h>

// Problem constants
#define BB   2
#define SS   2048
#define DM   1024
#define NH   16
#define HDIM 64

// Scratch (device globals: allocation-free)
__device__ uint32_t g_qt[BB * SS * DM];
__device__ uint32_t g_kt[BB * SS * DM];
__device__ uint32_t g_vthi[BB * NH * HDIM * SS];
__device__ uint32_t g_vtlo[BB * NH * HDIM * SS];

// ---------------------------------------------------------------------------
// Helpers
// ---------------------------------------------------------------------------
__device__ __forceinline__ void tf32_split(float x, uint32_t& hi, uint32_t& lo) {
    uint32_t xh = __float_as_uint(x) & 0xFFFFE000u;
    hi = xh;
    lo = __float_as_uint(x - __uint_as_float(xh));
}

__device__ __forceinline__ uint32_t cvt_tf32(float x) {
    uint32_t u;
    asm("cvt.rna.tf32.f32 %0, %1;" : "=r"(u) : "f"(x));
    return u;
}

__device__ __forceinline__ void mma_tf32(float* c,
                                         uint32_t a0, uint32_t a1, uint32_t a2, uint32_t a3,
                                         uint32_t b0, uint32_t b1) {
    asm volatile(
        "mma.sync.aligned.m16n8k8.row.col.f32.tf32.tf32.f32 "
        "{%0,%1,%2,%3}, {%4,%5,%6,%7}, {%8,%9}, {%0,%1,%2,%3};\n"
        : "+f"(c[0]), "+f"(c[1]), "+f"(c[2]), "+f"(c[3])
        : "r"(a0), "r"(a1), "r"(a2), "r"(a3), "r"(b0), "r"(b1));
}

__device__ __forceinline__ void cp_async16(void* smem, const void* gmem) {
    uint32_t s = (uint32_t)__cvta_generic_to_shared(smem);
    asm volatile("cp.async.ca.shared.global [%0], [%1], 16;\n" :: "r"(s), "l"(gmem));
}
__device__ __forceinline__ void cp_commit() {
    asm volatile("cp.async.commit_group;\n");
}
__device__ __forceinline__ void cp_wait1() {
    asm volatile("cp.async.wait_group 1;\n");
}
__device__ __forceinline__ void cp_wait0() {
    asm volatile("cp.async.wait_group 0;\n");
}

// ---------------------------------------------------------------------------
// Projection GEMMs. CTA tile 128x64, BK=16, 256 threads, warp 32x32.
// 3-stage cp.async pipeline on the smem tiles.
// ---------------------------------------------------------------------------
#define BM 128
#define BN 64
#define BK 16
#define KPAD 4
#define NSTG 3

__device__ __forceinline__ void gemm_load_stage(
    const float* __restrict__ X, const float* __restrict__ W,
    float (*As)[BK + KPAD], float (*Bs)[BK + KPAD],
    int m0, int n0, int k0, int K, int tid)
{
#pragma unroll
    for (int i = 0; i < 2; i++) {
        int f   = tid + i * 256;
        int row = f >> 2;
        int kq  = (f & 3) * 4;
        cp_async16(&As[row][kq], &X[(size_t)(m0 + row) * K + k0 + kq]);
    }
    {
        int row = tid >> 2;
        int kq  = (tid & 3) * 4;
        cp_async16(&Bs[row][kq], &W[(size_t)(n0 + row) * K + k0 + kq]);
    }
    cp_commit();
}

__global__ __launch_bounds__(256) void gemm_tf32_1p_tf32out(
    const float* __restrict__ X, const float* __restrict__ W,
    const float* __restrict__ bias, uint32_t* __restrict__ Y,
    int M, int N, int K, float oscale)
{
    __shared__ __align__(16) float As[NSTG][BM][BK + KPAD];
    __shared__ __align__(16) float Bs[NSTG][BN][BK + KPAD];

    const int tid  = threadIdx.x;
    const int warp = tid >> 5;
    const int lane = tid & 31;
    const int wm = (warp >> 1) * 32;
    const int wn = (warp & 1) * 32;
    const int g  = lane >> 2;
    const int tg = lane & 3;
    const int m0 = blockIdx.y * BM;
    const int n0 = blockIdx.x * BN;
    const int NIT = K / BK;

    float c[2][4][4];
#pragma unroll
    for (int mt = 0; mt < 2; mt++)
#pragma unroll
        for (int nt = 0; nt < 4; nt++)
#pragma unroll
            for (int r = 0; r < 4; r++) c[mt][nt][r] = 0.0f;

    gemm_load_stage(X, W, As[0], Bs[0], m0, n0, 0, K, tid);
    gemm_load_stage(X, W, As[1], Bs[1], m0, n0, BK, K, tid);

    for (int it = 0; it < NIT; it++) {
        if (it + 2 < NIT) cp_wait1(); else cp_wait0();
        __syncthreads();
        if (it + 2 < NIT)
            gemm_load_stage(X, W, As[(it + 2) % NSTG], Bs[(it + 2) % NSTG],
                            m0, n0, (it + 2) * BK, K, tid);

        const int st = it % NSTG;
#pragma unroll
        for (int ks = 0; ks < 2; ks++) {
            const int kb = ks * 8;
            uint32_t a[2][4];
#pragma unroll
            for (int mt = 0; mt < 2; mt++) {
                int r0 = wm + mt * 16;
                a[mt][0] = cvt_tf32(As[st][r0 + g    ][kb + tg    ]);
                a[mt][1] = cvt_tf32(As[st][r0 + g + 8][kb + tg    ]);
                a[mt][2] = cvt_tf32(As[st][r0 + g    ][kb + tg + 4]);
                a[mt][3] = cvt_tf32(As[st][r0 + g + 8][kb + tg + 4]);
            }
#pragma unroll
            for (int nt = 0; nt < 4; nt++) {
                int nr = wn + nt * 8 + g;
                uint32_t b0 = cvt_tf32(Bs[st][nr][kb + tg    ]);
                uint32_t b1 = cvt_tf32(Bs[st][nr][kb + tg + 4]);
#pragma unroll
                for (int mt = 0; mt < 2; mt++)
                    mma_tf32(c[mt][nt], a[mt][0], a[mt][1], a[mt][2], a[mt][3], b0, b1);
            }
        }
        __syncthreads();
    }

#pragma unroll
    for (int mt = 0; mt < 2; mt++) {
#pragma unroll
        for (int nt = 0; nt < 4; nt++) {
            int m = m0 + wm + mt * 16 + g;
            int n = n0 + wn + nt * 8 + tg * 2;
            float b0 = bias[n];
            float b1 = bias[n + 1];
            Y[(size_t)m * N + n]           = cvt_tf32((c[mt][nt][0] + b0) * oscale);
            Y[(size_t)m * N + n + 1]       = cvt_tf32((c[mt][nt][1] + b1) * oscale);
            Y[(size_t)(m + 8) * N + n]     = cvt_tf32((c[mt][nt][2] + b0) * oscale);
            Y[(size_t)(m + 8) * N + n + 1] = cvt_tf32((c[mt][nt][3] + b1) * oscale);
        }
    }
}

// 3-pass accurate GEMM, transposed + pre-split epilogue into hi/lo tf32 arrays
__global__ __launch_bounds__(256) void gemm_tf32_3p_vt_split(
    const float* __restrict__ X, const float* __restrict__ W,
    const float* __restrict__ bias,
    uint32_t* __restrict__ VTHI, uint32_t* __restrict__ VTLO,
    int M, int N, int K)
{
    __shared__ __align__(16) float As[NSTG][BM][BK + KPAD];
    __shared__ __align__(16) float Bs[NSTG][BN][BK + KPAD];

    const int tid  = threadIdx.x;
    const int warp = tid >> 5;
    const int lane = tid & 31;
    const int wm = (warp >> 1) * 32;
    const int wn = (warp & 1) * 32;
    const int g  = lane >> 2;
    const int tg = lane & 3;
    const int m0 = blockIdx.y * BM;
    const int n0 = blockIdx.x * BN;
    const int NIT = K / BK;

    float c[2][4][4];
#pragma unroll
    for (int mt = 0; mt < 2; mt++)
#pragma unroll
        for (int nt = 0; nt < 4; nt++)
#pragma unroll
            for (int r = 0; r < 4; r++) c[mt][nt][r] = 0.0f;

    gemm_load_stage(X, W, As[0], Bs[0], m0, n0, 0, K, tid);
    gemm_load_stage(X, W, As[1], Bs[1], m0, n0, BK, K, tid);

    for (int it = 0; it < NIT; it++) {
        if (it + 2 < NIT) cp_wait1(); else cp_wait0();
        __syncthreads();
        if (it + 2 < NIT)
            gemm_load_stage(X, W, As[(it + 2) % NSTG], Bs[(it + 2) % NSTG],
                            m0, n0, (it + 2) * BK, K, tid);

        const int st = it % NSTG;
#pragma unroll
        for (int ks = 0; ks < 2; ks++) {
            const int kb = ks * 8;
            uint32_t ahi[2][4], alo[2][4];
#pragma unroll
            for (int mt = 0; mt < 2; mt++) {
                int r0 = wm + mt * 16;
                tf32_split(As[st][r0 + g    ][kb + tg    ], ahi[mt][0], alo[mt][0]);
                tf32_split(As[st][r0 + g + 8][kb + tg    ], ahi[mt][1], alo[mt][1]);
                tf32_split(As[st][r0 + g    ][kb + tg + 4], ahi[mt][2], alo[mt][2]);
                tf32_split(As[st][r0 + g + 8][kb + tg + 4], ahi[mt][3], alo[mt][3]);
            }
#pragma unroll
            for (int nt = 0; nt < 4; nt++) {
                int nr = wn + nt * 8 + g;
                uint32_t bh0, bl0, bh1, bl1;
                tf32_split(Bs[st][nr][kb + tg    ], bh0, bl0);
                tf32_split(Bs[st][nr][kb + tg + 4], bh1, bl1);
#pragma unroll
                for (int mt = 0; mt < 2; mt++) {
                    mma_tf32(c[mt][nt], ahi[mt][0], ahi[mt][1], ahi[mt][2], ahi[mt][3], bh0, bh1);
                    mma_tf32(c[mt][nt], ahi[mt][0], ahi[mt][1], ahi[mt][2], ahi[mt][3], bl0, bl1);
                    mma_tf32(c[mt][nt], alo[mt][0], alo[mt][1], alo[mt][2], alo[mt][3], bh0, bh1);
                }
            }
        }
        __syncthreads();
    }

    // Transposed + split epilogue: m=(b,s), n=(h,d) -> [((b*NH+h)*HDIM+d)*SS + s]
#pragma unroll
    for (int mt = 0; mt < 2; mt++) {
#pragma unroll
        for (int nt = 0; nt < 4; nt++) {
            int m = m0 + wm + mt * 16 + g;
            int n = n0 + wn + nt * 8 + tg * 2;
            int bidx = m >> 11, s = m & 2047;
#pragma unroll
            for (int e = 0; e < 2; e++) {
                int nn = n + e;
                int hh = nn >> 6, dd = nn & 63;
                size_t base = (((size_t)(bidx * NH + hh)) * HDIM + dd) * SS;
                float bb = bias[nn];
#pragma unroll
                for (int rr = 0; rr < 2; rr++) {
                    float y = c[mt][nt][e + 2 * rr] + bb;
                    uint32_t hi = __float_as_uint(y) & 0xFFFFE000u;  // tf32-exact
                    float lo = y - __uint_as_float(hi);
                    VTHI[base + s + 8 * rr] = hi;
                    VTLO[base + s + 8 * rr] = cvt_tf32(lo);
                }
            }
        }
    }
}

// ---------------------------------------------------------------------------
// Tensor-core flash attention (TF32), causal. (unchanged from R6)
// ---------------------------------------------------------------------------
#define QT 128
#define KT 64
#define PSTR 68
#define FA_SMEM ((3 * 64 * PSTR + 4 * 32 * PSTR) * (int)sizeof(uint32_t))

__global__ __launch_bounds__(128) void flash_attn_tc(
    const uint32_t* __restrict__ Qt, const uint32_t* __restrict__ Kt,
    const uint32_t* __restrict__ VHI, const uint32_t* __restrict__ VLO,
    float* __restrict__ O)
{
    extern __shared__ uint32_t smu[];
    uint32_t* sK  = smu;
    uint32_t* sVh = smu + 64 * PSTR;
    uint32_t* sVl = smu + 2 * 64 * PSTR;
    uint32_t* sP  = smu + 3 * 64 * PSTR;

    const int tid  = threadIdx.x;
    const int w    = tid >> 5;
    const int lane = tid & 31;
    const int g    = lane >> 2;
    const int tg   = lane & 3;
    const int qt   = (int)gridDim.x - 1 - (int)blockIdx.x;
    const int h    = blockIdx.y;
    const int b    = blockIdx.z;
    const int qbase = qt * QT;
    const float NEG = -1.0e30f;

    const uint32_t* Qg = Qt + ((size_t)(b * SS) + qbase) * DM + h * HDIM;
    uint32_t qf[2][8][4];
#pragma unroll
    for (int mt = 0; mt < 2; mt++) {
        int r0 = w * 32 + mt * 16 + g;
#pragma unroll
        for (int ks = 0; ks < 8; ks++) {
            int cc = ks * 8 + tg;
            qf[mt][ks][0] = Qg[(size_t)(r0    ) * DM + cc    ];
            qf[mt][ks][1] = Qg[(size_t)(r0 + 8) * DM + cc    ];
            qf[mt][ks][2] = Qg[(size_t)(r0    ) * DM + cc + 4];
            qf[mt][ks][3] = Qg[(size_t)(r0 + 8) * DM + cc + 4];
        }
    }

    float of[2][8][4];
    float mrow[2][2], lrow[2][2];
#pragma unroll
    for (int mt = 0; mt < 2; mt++) {
        mrow[mt][0] = NEG; mrow[mt][1] = NEG;
        lrow[mt][0] = 0.f; lrow[mt][1] = 0.f;
#pragma unroll
        for (int nt = 0; nt < 8; nt++)
#pragma unroll
            for (int r = 0; r < 4; r++) of[mt][nt][r] = 0.f;
    }

    uint32_t* Pw = sP + w * 32 * PSTR;
    const int nkt = 2 * qt + 2;

    for (int kt = 0; kt < nkt; kt++) {
        __syncthreads();
        const uint32_t* Kg = Kt  + ((size_t)(b * SS) + kt * KT) * DM + h * HDIM;
        size_t vbase = ((size_t)(b * NH + h) * HDIM) * SS + kt * KT;
#pragma unroll
        for (int i = 0; i < 8; i++) {
            int f = tid + i * 128;
            int row = f >> 4, c4 = (f & 15) * 4;
            *(uint4*)&sK[row * PSTR + c4]  = *(const uint4*)&Kg[(size_t)row * DM + c4];
            *(uint4*)&sVh[row * PSTR + c4] = *(const uint4*)&VHI[vbase + (size_t)row * SS + c4];
            *(uint4*)&sVl[row * PSTR + c4] = *(const uint4*)&VLO[vbase + (size_t)row * SS + c4];
        }
        __syncthreads();

        if (kt * KT > qbase + w * 32 + 31) continue;

        float s[2][8][4];
#pragma unroll
        for (int mt = 0; mt < 2; mt++)
#pragma unroll
            for (int nt = 0; nt < 8; nt++)
#pragma unroll
                for (int r = 0; r < 4; r++) s[mt][nt][r] = 0.f;

#pragma unroll
        for (int ks = 0; ks < 8; ks++) {
#pragma unroll
            for (int nt = 0; nt < 8; nt++) {
                int nr = nt * 8 + g;
                uint32_t b0 = sK[nr * PSTR + ks * 8 + tg    ];
                uint32_t b1 = sK[nr * PSTR + ks * 8 + tg + 4];
                mma_tf32(s[0][nt], qf[0][ks][0], qf[0][ks][1], qf[0][ks][2], qf[0][ks][3], b0, b1);
                mma_tf32(s[1][nt], qf[1][ks][0], qf[1][ks][1], qf[1][ks][2], qf[1][ks][3], b0, b1);
            }
        }

        if (kt >= 2 * qt) {
#pragma unroll
            for (int mt = 0; mt < 2; mt++) {
                int row0 = qbase + w * 32 + mt * 16 + g;
#pragma unroll
                for (int nt = 0; nt < 8; nt++) {
                    int col = kt * KT + nt * 8 + 2 * tg;
                    if (col     > row0    ) s[mt][nt][0] = NEG;
                    if (col + 1 > row0    ) s[mt][nt][1] = NEG;
                    if (col     > row0 + 8) s[mt][nt][2] = NEG;
                    if (col + 1 > row0 + 8) s[mt][nt][3] = NEG;
                }
            }
        }

#pragma unroll
        for (int mt = 0; mt < 2; mt++) {
            float rm0 = NEG, rm1 = NEG;
#pragma unroll
            for (int nt = 0; nt < 8; nt++) {
                rm0 = fmaxf(rm0, fmaxf(s[mt][nt][0], s[mt][nt][1]));
                rm1 = fmaxf(rm1, fmaxf(s[mt][nt][2], s[mt][nt][3]));
            }
#pragma unroll
            for (int d = 1; d < 4; d <<= 1) {
                rm0 = fmaxf(rm0, __shfl_xor_sync(0xffffffffu, rm0, d));
                rm1 = fmaxf(rm1, __shfl_xor_sync(0xffffffffu, rm1, d));
            }
            float mn0 = fmaxf(mrow[mt][0], rm0);
            float mn1 = fmaxf(mrow[mt][1], rm1);
            float corr0 = __expf(mrow[mt][0] - mn0);
            float corr1 = __expf(mrow[mt][1] - mn1);
            float rs0 = 0.f, rs1 = 0.f;
#pragma unroll
            for (int nt = 0; nt < 8; nt++) {
                s[mt][nt][0] = __expf(s[mt][nt][0] - mn0);
                s[mt][nt][1] = __expf(s[mt][nt][1] - mn0);
                s[mt][nt][2] = __expf(s[mt][nt][2] - mn1);
                s[mt][nt][3] = __expf(s[mt][nt][3] - mn1);
                rs0 += s[mt][nt][0] + s[mt][nt][1];
                rs1 += s[mt][nt][2] + s[mt][nt][3];
            }
#pragma unroll
            for (int d = 1; d < 4; d <<= 1) {
                rs0 += __shfl_xor_sync(0xffffffffu, rs0, d);
                rs1 += __shfl_xor_sync(0xffffffffu, rs1, d);
            }
            lrow[mt][0] = lrow[mt][0] * corr0 + rs0;
            lrow[mt][1] = lrow[mt][1] * corr1 + rs1;
            mrow[mt][0] = mn0;
            mrow[mt][1] = mn1;
#pragma unroll
            for (int nt = 0; nt < 8; nt++) {
                of[mt][nt][0] *= corr0;
                of[mt][nt][1] *= corr0;
                of[mt][nt][2] *= corr1;
                of[mt][nt][3] *= corr1;
            }
            int pr = mt * 16 + g;
#pragma unroll
            for (int nt = 0; nt < 8; nt++) {
                uint2 p01 = make_uint2(cvt_tf32(s[mt][nt][0]), cvt_tf32(s[mt][nt][1]));
                uint2 p23 = make_uint2(cvt_tf32(s[mt][nt][2]), cvt_tf32(s[mt][nt][3]));
                *(uint2*)&Pw[(pr    ) * PSTR + nt * 8 + 2 * tg] = p01;
                *(uint2*)&Pw[(pr + 8) * PSTR + nt * 8 + 2 * tg] = p23;
            }
        }
        __syncwarp();

#pragma unroll
        for (int ks = 0; ks < 8; ks++) {
            uint32_t a[2][4];
#pragma unroll
            for (int mt = 0; mt < 2; mt++) {
                int pr = mt * 16 + g;
                int cc = ks * 8 + tg;
                a[mt][0] = Pw[(pr    ) * PSTR + cc    ];
                a[mt][1] = Pw[(pr + 8) * PSTR + cc    ];
                a[mt][2] = Pw[(pr    ) * PSTR + cc + 4];
                a[mt][3] = Pw[(pr + 8) * PSTR + cc + 4];
            }
#pragma unroll
            for (int nt = 0; nt < 8; nt++) {
                int nr = nt * 8 + g;
                uint32_t bh0 = sVh[nr * PSTR + ks * 8 + tg    ];
                uint32_t bh1 = sVh[nr * PSTR + ks * 8 + tg + 4];
                uint32_t bl0 = sVl[nr * PSTR + ks * 8 + tg    ];
                uint32_t bl1 = sVl[nr * PSTR + ks * 8 + tg + 4];
#pragma unroll
                for (int mt = 0; mt < 2; mt++) {
                    mma_tf32(of[mt][nt], a[mt][0], a[mt][1], a[mt][2], a[mt][3], bh0, bh1);
                    mma_tf32(of[mt][nt], a[mt][0], a[mt][1], a[mt][2], a[mt][3], bl0, bl1);
                }
            }
        }
        __syncwarp();
    }

    float* Og = O + ((size_t)(b * SS) + qbase) * DM + h * HDIM;
#pragma unroll
    for (int mt = 0; mt < 2; mt++) {
        float inv0 = 1.0f / lrow[mt][0];
        float inv1 = 1.0f / lrow[mt][1];
        int r0 = w * 32 + mt * 16 + g;
#pragma unroll
        for (int nt = 0; nt < 8; nt++) {
            int cc = nt * 8 + 2 * tg;
            *(float2*)&Og[(size_t)(r0    ) * DM + cc] =
                make_float2(of[mt][nt][0] * inv0, of[mt][nt][1] * inv0);
            *(float2*)&Og[(size_t)(r0 + 8) * DM + cc] =
                make_float2(of[mt][nt][2] * inv1, of[mt][nt][3] * inv1);
        }
    }
}

// ---------------------------------------------------------------------------
// kernel_launch
// ---------------------------------------------------------------------------
extern "C" void kernel_launch(void* const* d_in, const int* in_sizes, int n_in,
                              void* d_out, int out_size)
{
    const float* qx = (const float*)d_in[0];
    const float* kx = (const float*)d_in[1];
    const float* vx = (const float*)d_in[2];
    const float* Wq = (const float*)d_in[4];
    const float* bq = (const float*)d_in[5];
    const float* Wk = (const float*)d_in[6];
    const float* bk = (const float*)d_in[7];
    const float* Wv = (const float*)d_in[8];
    const float* bv = (const float*)d_in[9];
    float* out = (float*)d_out;

    uint32_t *gq, *gk, *gvh, *gvl;
    cudaGetSymbolAddress((void**)&gq,  g_qt);
    cudaGetSymbolAddress((void**)&gk,  g_kt);
    cudaGetSymbolAddress((void**)&gvh, g_vthi);
    cudaGetSymbolAddress((void**)&gvl, g_vtlo);

    const int M = BB * SS;   // 4096
    const int N = DM;        // 1024
    const int K = DM;        // 1024

    dim3 ggrid(N / BN, M / BM);   // (16, 32)
    gemm_tf32_1p_tf32out<<<ggrid, 256>>>(qx, Wq, bq, gq, M, N, K, 0.03125f);
    gemm_tf32_1p_tf32out<<<ggrid, 256>>>(kx, Wk, bk, gk, M, N, K, 1.0f);
    gemm_tf32_3p_vt_split<<<ggrid, 256>>>(vx, Wv, bv, gvh, gvl, M, N, K);

    cudaFuncSetAttribute(flash_attn_tc,
                         cudaFuncAttributeMaxDynamicSharedMemorySize, FA_SMEM);
    dim3 agrid(SS / QT, NH, BB);    // (16, 16, 2)
    flash_attn_tc<<<agrid, 128, FA_SMEM>>>(gq, gk, gvh, gvl, out);
}